// round 14
// baseline (speedup 1.0000x reference)
#include <cuda_runtime.h>

#define NB 32
#define NPG 4096
#define NN (NB*NPG)          /* 131072 */
#define FIN 64
#define CC 128
#define KK 32
#define JJ 40
#define NXBLK (NN/64)        /* 2048 */
#define NYBLK ((NB*JJ)/64)   /* 20 */
#define NXB2 (NN/128)        /* 1024 */
#define NXB4 (NN/256)        /* 512 */

// ---------------- scratch (static device globals; no allocation) -------------
__device__ float    g_x[NN*CC];        // xs (raw, then normalized-domain)
__device__ float    g_I[NN*JJ];        // raw I
__device__ float    g_ys[NB*JJ*CC];    // ys raw
__device__ float    g_yp[NB*JJ*KK];    // y_p
__device__ double   g_acc[4];          // sx, sx2, sy, sy2
__device__ unsigned g_maxb[2][NB*JJ];
__device__ float    g_sumb[2][NB*JJ];

__device__ __forceinline__ unsigned ordf(float f){
    unsigned u = __float_as_uint(f);
    return (u & 0x80000000u) ? ~u : (u | 0x80000000u);
}
__device__ __forceinline__ float unordf(unsigned u){
    return (u & 0x80000000u) ? __uint_as_float(u & 0x7fffffffu)
                             : __uint_as_float(~u);
}
__device__ __forceinline__ float sigm(float t){ return 1.f/(1.f+__expf(-t)); }

__device__ __forceinline__ void get_stats(int which, float& m, float& r){
    double s  = g_acc[which*2+0];
    double s2 = g_acc[which*2+1];
    double cnt = which ? (double)(NB*JJ)*(double)CC : (double)NN*(double)CC;
    double mu = s/cnt;
    double var = s2/cnt - mu*mu;
    m = (float)mu;
    r = (float)rsqrt(var + 1e-5);
}

// ---------------- init: zero stat buffers ------------------------------------
__global__ void k_init(){
    int tid = threadIdx.x;
    if (tid < 4) g_acc[tid] = 0.0;
    for (int i = tid; i < 2*NB*JJ; i += 256){
        ((unsigned*)g_maxb)[i] = 0u;
        ((float*)g_sumb)[i]    = 0.f;
    }
}

// ---------------- input GEMM: out = A[M,64] @ W^T[64,128] + b ----------------
__global__ __launch_bounds__(256) void k_in_gemm(
    const float* __restrict__ node, const float* __restrict__ frag,
    const float* __restrict__ W, const float* __restrict__ bias)
{
    int bx = blockIdx.x;
    bool isY = (bx >= NXBLK);
    const float* __restrict__ A   = isY ? frag : node;
    float* __restrict__       out = isY ? g_ys : g_x;
    long m0 = (long)(isY ? bx - NXBLK : bx) * 64;

    __shared__ __align__(16) float sW[FIN*CC];  // [k][n]
    __shared__ __align__(16) float sA[64*FIN];  // [m][k]
    int tid = threadIdx.x;

    for (int i = tid; i < FIN*CC; i += 256){
        int n = i >> 6, k = i & 63;
        sW[k*CC + n] = W[i];
    }
    for (int i = tid; i < 64*FIN; i += 256) sA[i] = A[m0*FIN + i];
    __syncthreads();

    int c  = (tid & 31) * 4;
    int mg = (tid >> 5) * 8;
    float4 bb = *(const float4*)&bias[c];
    float4 acc[8];
    #pragma unroll
    for (int r = 0; r < 8; r++) acc[r] = bb;

    #pragma unroll 4
    for (int k = 0; k < FIN; k += 4){
        float4 w0 = *(const float4*)&sW[(k+0)*CC + c];
        float4 w1 = *(const float4*)&sW[(k+1)*CC + c];
        float4 w2 = *(const float4*)&sW[(k+2)*CC + c];
        float4 w3 = *(const float4*)&sW[(k+3)*CC + c];
        #pragma unroll
        for (int r = 0; r < 8; r++){
            float4 a = *(const float4*)&sA[(mg+r)*FIN + k];
            acc[r].x += a.x*w0.x + a.y*w1.x + a.z*w2.x + a.w*w3.x;
            acc[r].y += a.x*w0.y + a.y*w1.y + a.z*w2.y + a.w*w3.y;
            acc[r].z += a.x*w0.z + a.y*w1.z + a.z*w2.z + a.w*w3.z;
            acc[r].w += a.x*w0.w + a.y*w1.w + a.z*w2.w + a.w*w3.w;
        }
    }
    float s = 0.f, s2 = 0.f;
    #pragma unroll
    for (int r = 0; r < 8; r++){
        *(float4*)&out[(m0+mg+r)*CC + c] = acc[r];
        s  += acc[r].x + acc[r].y + acc[r].z + acc[r].w;
        s2 += acc[r].x*acc[r].x + acc[r].y*acc[r].y
            + acc[r].z*acc[r].z + acc[r].w*acc[r].w;
    }
    __syncthreads();
    float* red = sA;            // reuse
    red[tid] = s; red[256+tid] = s2;
    __syncthreads();
    for (int off = 128; off > 0; off >>= 1){
        if (tid < off){ red[tid] += red[tid+off]; red[256+tid] += red[256+tid+off]; }
        __syncthreads();
    }
    if (tid == 0){
        atomicAdd(&g_acc[isY ? 2 : 0], (double)red[0]);
        atomicAdd(&g_acc[isY ? 3 : 1], (double)red[256]);
    }
}

// ---------------- y_p = relu(q * relu(LN(ys) @ V)) ---------------------------
__global__ __launch_bounds__(256) void k_yp(const float* __restrict__ V,
                                            const float* __restrict__ q){
    int tid = threadIdx.x;
    int row = blockIdx.x*8 + (tid >> 5);   // grid 160 -> 1280 rows
    int k = tid & 31;
    float m, r; get_stats(1, m, r);
    const float* ys = &g_ys[row*CC];
    float acc = 0.f;
    #pragma unroll 4
    for (int d = 0; d < CC; d++) acc += (ys[d]-m)*r * V[d*KK + k];
    float t = fmaxf(acc, 0.f);
    g_yp[row*KK + k] = fmaxf(q[k]*t, 0.f);
}

// ---------------- kA: x_p = relu(x@U), I = x_p @ y_p^T ; FINAL fuses readout --
// 256-row tiles; x staged in four 32-col slices; 8 rows x 4 k per thread.
template<bool FINAL, bool NORM>
__global__ __launch_bounds__(256, 3) void kA(const float* __restrict__ U,
                                             int layer, float* __restrict__ outp)
{
    extern __shared__ __align__(16) float S[];
    float* UsS = S;             // CC*KK floats (16KB), [d][k]
    float* xS  = S + CC*KK;     // 256*32 floats (32KB), xor-swizzled slice
    int tid = threadIdx.x;
    long m0 = (long)blockIdx.x * 256;
    int b = (int)(m0 >> 12);

    float mean = 0.f, rstd = 1.f;
    if (NORM) get_stats(0, mean, rstd);

    for (int i = tid; i < CC*KK; i += 256) UsS[i] = U[i];

    int kg = (tid & 7) * 4;          // 4 k-cols
    int rg = (tid >> 3) * 8;         // 8 rows
    int sw = ((rg >> 3) & 3) * 4;    // constant per thread
    float4 acc[8];
    #pragma unroll
    for (int i = 0; i < 8; i++) acc[i] = make_float4(0.f,0.f,0.f,0.f);

    #pragma unroll
    for (int dh = 0; dh < 4; dh++){
        __syncthreads();
        // stage slice: 256 rows x 32 cols
        #pragma unroll
        for (int t = 0; t < 8; t++){
            int i = tid + t*256;        // 0..2047
            int m = i >> 3; int c4 = (i & 7) * 4;
            float4 v = *(const float4*)&g_x[(m0+m)*CC + dh*32 + c4];
            if (NORM){
                v.x = (v.x-mean)*rstd; v.y = (v.y-mean)*rstd;
                v.z = (v.z-mean)*rstd; v.w = (v.w-mean)*rstd;
            }
            *(float4*)&xS[m*32 + (c4 ^ (((m >> 3) & 3) * 4))] = v;
        }
        __syncthreads();

        #pragma unroll 4
        for (int d = 0; d < 32; d += 4){
            int du = dh*32 + d;
            float4 u0 = *(const float4*)&UsS[(du+0)*KK + kg];
            float4 u1 = *(const float4*)&UsS[(du+1)*KK + kg];
            float4 u2 = *(const float4*)&UsS[(du+2)*KK + kg];
            float4 u3 = *(const float4*)&UsS[(du+3)*KK + kg];
            #pragma unroll
            for (int i = 0; i < 8; i++){
                float4 xr = *(const float4*)&xS[(rg+i)*32 + (d ^ sw)];
                acc[i].x += xr.x*u0.x + xr.y*u1.x + xr.z*u2.x + xr.w*u3.x;
                acc[i].y += xr.x*u0.y + xr.y*u1.y + xr.z*u2.y + xr.w*u3.y;
                acc[i].z += xr.x*u0.z + xr.y*u1.z + xr.z*u2.z + xr.w*u3.z;
                acc[i].w += xr.x*u0.w + xr.y*u1.w + xr.z*u2.w + xr.w*u3.w;
            }
        }
    }
    #pragma unroll
    for (int i = 0; i < 8; i++){
        acc[i].x = fmaxf(acc[i].x, 0.f); acc[i].y = fmaxf(acc[i].y, 0.f);
        acc[i].z = fmaxf(acc[i].z, 0.f); acc[i].w = fmaxf(acc[i].w, 0.f);
    }
    __syncthreads();

    // phase2 smem repartition (63.7KB peak)
    float* xpS  = S;                           // [256][36]
    float* ypS  = S + 256*36;                  // [40][36]
    float* iS   = ypS + 40*36;                 // [128*40] (one half at a time)
    float* sred = iS + 128*40;                 // [160]

    #pragma unroll
    for (int i = 0; i < 8; i++)
        *(float4*)&xpS[(rg+i)*36 + kg] = acc[i];
    for (int i = tid; i < JJ*KK; i += 256){
        int j = i >> 5, k2 = i & 31;
        ypS[j*36 + k2] = g_yp[b*JJ*KK + i];
    }
    __syncthreads();

    // phase2: two halves of 128 rows each
    #pragma unroll
    for (int h = 0; h < 2; h++){
        {
            int mgt = tid >> 3;          // 0..31 -> local rows mgt*4..+3
            int jg  = (tid & 7) * 5;     // j base
            float a[4][5];
            #pragma unroll
            for (int i = 0; i < 4; i++)
                #pragma unroll
                for (int jj = 0; jj < 5; jj++) a[i][jj] = 0.f;
            #pragma unroll
            for (int k = 0; k < KK; k += 4){
                float4 xp4[4], yp4[5];
                #pragma unroll
                for (int i = 0; i < 4; i++)
                    xp4[i] = *(const float4*)&xpS[(h*128 + mgt*4+i)*36 + k];
                #pragma unroll
                for (int jj = 0; jj < 5; jj++)
                    yp4[jj] = *(const float4*)&ypS[(jg+jj)*36 + k];
                #pragma unroll
                for (int i = 0; i < 4; i++)
                    #pragma unroll
                    for (int jj = 0; jj < 5; jj++)
                        a[i][jj] += xp4[i].x*yp4[jj].x + xp4[i].y*yp4[jj].y
                                  + xp4[i].z*yp4[jj].z + xp4[i].w*yp4[jj].w;
            }
            #pragma unroll
            for (int i = 0; i < 4; i++)
                #pragma unroll
                for (int jj = 0; jj < 5; jj++)
                    iS[(mgt*4+i)*40 + jg + jj] = a[i][jj];
        }
        __syncthreads();

        if (!FINAL){
            // coalesced I writeback for this half
            const float4* iv4 = (const float4*)iS;
            float4* Ig4 = (float4*)(g_I + (m0 + h*128)*JJ);
            #pragma unroll
            for (int t = 0; t < 5; t++) Ig4[tid + t*256] = iv4[tid + t*256];
            // column max for this half
            if (tid < 160){
                int j = tid % 40, seg = tid / 40;
                float mx = -3.4e38f;
                #pragma unroll 8
                for (int r = 0; r < 32; r++) mx = fmaxf(mx, iS[(seg*32+r)*40 + j]);
                sred[tid] = mx;
            }
            __syncthreads();
            if (tid < 40){
                float mx = fmaxf(fmaxf(sred[tid], sred[40+tid]),
                                 fmaxf(sred[80+tid], sred[120+tid]));
                atomicMax(&g_maxb[layer][b*JJ + tid], ordf(mx));
            }
        } else {
            // p = I @ y_p ; out = sigmoid(dot(x_p, p)); 2 threads per node
            int m  = tid >> 1;
            int kh = (tid & 1) * 16;
            float4 p0 = make_float4(0.f,0.f,0.f,0.f), p1 = p0, p2 = p0, p3 = p0;
            #pragma unroll
            for (int j = 0; j < JJ; j++){
                float iv = iS[m*40 + j];
                float4 y0 = *(const float4*)&ypS[j*36 + kh + 0];
                float4 y1 = *(const float4*)&ypS[j*36 + kh + 4];
                float4 y2 = *(const float4*)&ypS[j*36 + kh + 8];
                float4 y3 = *(const float4*)&ypS[j*36 + kh + 12];
                p0.x += iv*y0.x; p0.y += iv*y0.y; p0.z += iv*y0.z; p0.w += iv*y0.w;
                p1.x += iv*y1.x; p1.y += iv*y1.y; p1.z += iv*y1.z; p1.w += iv*y1.w;
                p2.x += iv*y2.x; p2.y += iv*y2.y; p2.z += iv*y2.z; p2.w += iv*y2.w;
                p3.x += iv*y3.x; p3.y += iv*y3.y; p3.z += iv*y3.z; p3.w += iv*y3.w;
            }
            int mr = h*128 + m;
            float4 x0 = *(const float4*)&xpS[mr*36 + kh + 0];
            float4 x1 = *(const float4*)&xpS[mr*36 + kh + 4];
            float4 x2 = *(const float4*)&xpS[mr*36 + kh + 8];
            float4 x3 = *(const float4*)&xpS[mr*36 + kh + 12];
            float dot = x0.x*p0.x + x0.y*p0.y + x0.z*p0.z + x0.w*p0.w
                      + x1.x*p1.x + x1.y*p1.y + x1.z*p1.z + x1.w*p1.w
                      + x2.x*p2.x + x2.y*p2.y + x2.z*p2.z + x2.w*p2.w
                      + x3.x*p3.x + x3.y*p3.y + x3.z*p3.z + x3.w*p3.w;
            dot += __shfl_down_sync(0xffffffffu, dot, 1);
            if (!(tid & 1)) outp[m0 + h*128 + m] = sigm(dot);
        }
        __syncthreads();
    }
}

// ---------------- kBl: column sums of exp(I - max) ---------------------------
__global__ __launch_bounds__(256) void kBl(int layer){
    __shared__ float mx[JJ];
    __shared__ __align__(16) float eS[128*JJ];
    __shared__ float sred[160];
    int tid = threadIdx.x;
    long m0 = (long)blockIdx.x * 128;
    int b = (int)(m0 >> 12);
    if (tid < JJ) mx[tid] = unordf(g_maxb[layer][b*JJ + tid]);
    __syncthreads();
    const float4* Ig4 = (const float4*)(g_I + m0*JJ);
    #pragma unroll
    for (int t = 0; t < 5; t++){
        int i4 = tid + t*256;
        float4 v = Ig4[i4];
        int base = i4*4;
        v.x = __expf(v.x - mx[(base+0) % 40]);
        v.y = __expf(v.y - mx[(base+1) % 40]);
        v.z = __expf(v.z - mx[(base+2) % 40]);
        v.w = __expf(v.w - mx[(base+3) % 40]);
        *(float4*)&eS[base] = v;
    }
    __syncthreads();
    if (tid < 160){
        int j = tid % 40, seg = tid / 40;
        float s = 0.f;
        #pragma unroll 8
        for (int r = 0; r < 32; r++) s += eS[(seg*32+r)*40 + j];
        sred[tid] = s;
    }
    __syncthreads();
    if (tid < 40)
        atomicAdd(&g_sumb[layer][b*JJ + tid],
                  sred[tid] + sred[40+tid] + sred[80+tid] + sred[120+tid]);
}

// ---------------- kC: h=relu(A@y_p); h@V^T; gate; x update -------------------
template<bool NORM>
__global__ __launch_bounds__(256) void kC(const float* __restrict__ V,
                                          const float* __restrict__ gW,
                                          const float* __restrict__ gb, int layer)
{
    __shared__ __align__(16) float eS[64*JJ];     // softmax weights
    __shared__ __align__(16) float ypS[JJ*33];
    __shared__ __align__(16) float HS[64*KK];
    __shared__ __align__(16) float VtS[KK*CC];    // [k][d]
    __shared__ float invs[JJ];
    __shared__ float mxs[JJ];
    int tid = threadIdx.x;
    long m0 = (long)blockIdx.x * 64;
    int b = (int)(m0 >> 12);

    float mean = 0.f, rstd = 1.f;
    if (NORM) get_stats(0, mean, rstd);

    if (tid < JJ){
        invs[tid] = 1.f / g_sumb[layer][b*JJ + tid];
        mxs[tid]  = unordf(g_maxb[layer][b*JJ + tid]);
    }
    for (int i = tid; i < JJ*KK; i += 256){
        int j = i >> 5, k = i & 31;
        ypS[j*33 + k] = g_yp[b*JJ*KK + i];
    }
    for (int i = tid; i < KK*CC; i += 256){
        int d = i >> 5, k = i & 31;
        VtS[k*CC + d] = V[i];
    }
    __syncthreads();
    const float* Ig = &g_I[m0*JJ];
    #pragma unroll
    for (int t = 0; t < 10; t++){
        int idx = tid + t*256;
        int j = idx % 40;
        eS[idx] = __expf(Ig[idx] - mxs[j]) * invs[j];
    }
    __syncthreads();

    // H[m][k] = relu(sum_j a * yp), float4 over j
    int k = tid & 31;
    int mg = (tid >> 5) * 8;
    float h[8];
    #pragma unroll
    for (int r = 0; r < 8; r++) h[r] = 0.f;
    #pragma unroll
    for (int j = 0; j < JJ; j += 4){
        float yv0 = ypS[(j+0)*33 + k];
        float yv1 = ypS[(j+1)*33 + k];
        float yv2 = ypS[(j+2)*33 + k];
        float yv3 = ypS[(j+3)*33 + k];
        #pragma unroll
        for (int r = 0; r < 8; r++){
            float4 e4 = *(const float4*)&eS[(mg+r)*40 + j];
            h[r] += e4.x*yv0 + e4.y*yv1 + e4.z*yv2 + e4.w*yv3;
        }
    }
    #pragma unroll
    for (int r = 0; r < 8; r++) HS[(mg+r)*KK + k] = fmaxf(h[r], 0.f);
    __syncthreads();

    // hC = H @ V^T ; gate ; update
    int d4 = (tid & 31) * 4;
    float4 xv[8], acc[8];
    #pragma unroll
    for (int r = 0; r < 8; r++){
        xv[r] = *(const float4*)&g_x[(m0+mg+r)*CC + d4];
        if (NORM){
            xv[r].x = (xv[r].x-mean)*rstd; xv[r].y = (xv[r].y-mean)*rstd;
            xv[r].z = (xv[r].z-mean)*rstd; xv[r].w = (xv[r].w-mean)*rstd;
        }
        acc[r] = make_float4(0.f,0.f,0.f,0.f);
    }
    #pragma unroll 8
    for (int k2 = 0; k2 < KK; k2++){
        float4 vv = *(const float4*)&VtS[k2*CC + d4];
        #pragma unroll
        for (int r = 0; r < 8; r++){
            float hh = HS[(mg+r)*KK + k2];
            acc[r].x += hh*vv.x; acc[r].y += hh*vv.y;
            acc[r].z += hh*vv.z; acc[r].w += hh*vv.w;
        }
    }
    float4 g1 = *(const float4*)&gW[d4];
    float4 g2 = *(const float4*)&gW[CC + d4];
    float gbv = gb[0];
    #pragma unroll
    for (int r = 0; r < 8; r++){
        float t = xv[r].x*g1.x + xv[r].y*g1.y + xv[r].z*g1.z + xv[r].w*g1.w
                + acc[r].x*g2.x + acc[r].y*g2.y + acc[r].z*g2.z + acc[r].w*g2.w;
        #pragma unroll
        for (int off = 16; off >= 1; off >>= 1)
            t += __shfl_xor_sync(0xffffffffu, t, off);
        float z = sigm(t + gbv);
        float4 nx;
        nx.x = xv[r].x + z*(acc[r].x - xv[r].x);
        nx.y = xv[r].y + z*(acc[r].y - xv[r].y);
        nx.z = xv[r].z + z*(acc[r].z - xv[r].z);
        nx.w = xv[r].w + z*(acc[r].w - xv[r].w);
        *(float4*)&g_x[(m0+mg+r)*CC + d4] = nx;
    }
}

// ---------------- launch ------------------------------------------------------
extern "C" void kernel_launch(void* const* d_in, const int* in_sizes, int n_in,
                              void* d_out, int out_size)
{
    const float* node = (const float*)d_in[0];
    const float* frag = (const float*)d_in[1];
    const float* Wi   = (const float*)d_in[2];
    const float* bi   = (const float*)d_in[3];
    const float* U    = (const float*)d_in[4];
    const float* V    = (const float*)d_in[5];
    const float* q    = (const float*)d_in[6];
    const float* gW   = (const float*)d_in[7];
    const float* gb   = (const float*)d_in[8];
    float* out = (float*)d_out;

    // phase1: 16KB U + 32KB x slice; phase2: 256*36 + 40*36 + 128*40 + 160 floats
    const int SMEM_A = (256*36 + 40*36 + 128*40 + 160) * 4;   // 63744 bytes
    cudaFuncSetAttribute((const void*)kA<false,true >,
                         cudaFuncAttributeMaxDynamicSharedMemorySize, SMEM_A);
    cudaFuncSetAttribute((const void*)kA<false,false>,
                         cudaFuncAttributeMaxDynamicSharedMemorySize, SMEM_A);
    cudaFuncSetAttribute((const void*)kA<true ,false>,
                         cudaFuncAttributeMaxDynamicSharedMemorySize, SMEM_A);

    k_init<<<1, 256>>>();
    k_in_gemm<<<NXBLK + NYBLK, 256>>>(node, frag, Wi, bi);
    k_yp<<<160, 256>>>(V, q);

    // layer 0 (normalize on the fly)
    kA<false,true ><<<NXB4, 256, SMEM_A>>>(U, 0, nullptr);
    kBl<<<NXB2, 256>>>(0);
    kC<true ><<<NXBLK, 256>>>(V, gW, gb, 0);
    // layer 1
    kA<false,false><<<NXB4, 256, SMEM_A>>>(U, 1, nullptr);
    kBl<<<NXB2, 256>>>(1);
    kC<false><<<NXBLK, 256>>>(V, gW, gb, 1);
    // layer 2 (final, fused readout)
    kA<true ,false><<<NXB4, 256, SMEM_A>>>(U, 0, out);
}

// round 15
// speedup vs baseline: 1.1260x; 1.1260x over previous
#include <cuda_runtime.h>

#define NB 32
#define NPG 4096
#define NN (NB*NPG)          /* 131072 */
#define FIN 64
#define CC 128
#define KK 32
#define JJ 40
#define NXBLK (NN/64)        /* 2048 */
#define NYBLK ((NB*JJ)/64)   /* 20 */
#define NXB2 (NN/128)        /* 1024 */

// ---------------- scratch (static device globals; no allocation) -------------
__device__ float    g_x[NN*CC];        // xs (raw, then normalized-domain)
__device__ float    g_I[NN*JJ];        // raw I
__device__ float    g_ys[NB*JJ*CC];    // ys raw
__device__ float    g_yp[NB*JJ*KK];    // y_p
__device__ double   g_acc[4];          // sx, sx2, sy, sy2
__device__ float2   g_tstat[2][NXB2*JJ]; // per-tile (colmax, expsum)
__device__ float    g_maxf[2][NB*JJ];  // merged per-graph colmax
__device__ float    g_sumb[2][NB*JJ];  // merged per-graph expsum

__device__ __forceinline__ float sigm(float t){ return 1.f/(1.f+__expf(-t)); }

__device__ __forceinline__ void get_stats(int which, float& m, float& r){
    double s  = g_acc[which*2+0];
    double s2 = g_acc[which*2+1];
    double cnt = which ? (double)(NB*JJ)*(double)CC : (double)NN*(double)CC;
    double mu = s/cnt;
    double var = s2/cnt - mu*mu;
    m = (float)mu;
    r = (float)rsqrt(var + 1e-5);
}

// ---------------- init: zero LN accumulators ---------------------------------
__global__ void k_init(){
    if (threadIdx.x < 4) g_acc[threadIdx.x] = 0.0;
}

// ---------------- input GEMM: out = A[M,64] @ W^T[64,128] + b ----------------
__global__ __launch_bounds__(256) void k_in_gemm(
    const float* __restrict__ node, const float* __restrict__ frag,
    const float* __restrict__ W, const float* __restrict__ bias)
{
    int bx = blockIdx.x;
    bool isY = (bx >= NXBLK);
    const float* __restrict__ A   = isY ? frag : node;
    float* __restrict__       out = isY ? g_ys : g_x;
    long m0 = (long)(isY ? bx - NXBLK : bx) * 64;

    __shared__ __align__(16) float sW[FIN*CC];  // [k][n]
    __shared__ __align__(16) float sA[64*FIN];  // [m][k]
    int tid = threadIdx.x;

    for (int i = tid; i < FIN*CC; i += 256){
        int n = i >> 6, k = i & 63;
        sW[k*CC + n] = W[i];
    }
    for (int i = tid; i < 64*FIN; i += 256) sA[i] = A[m0*FIN + i];
    __syncthreads();

    int c  = (tid & 31) * 4;
    int mg = (tid >> 5) * 8;
    float4 bb = *(const float4*)&bias[c];
    float4 acc[8];
    #pragma unroll
    for (int r = 0; r < 8; r++) acc[r] = bb;

    #pragma unroll 4
    for (int k = 0; k < FIN; k += 4){
        float4 w0 = *(const float4*)&sW[(k+0)*CC + c];
        float4 w1 = *(const float4*)&sW[(k+1)*CC + c];
        float4 w2 = *(const float4*)&sW[(k+2)*CC + c];
        float4 w3 = *(const float4*)&sW[(k+3)*CC + c];
        #pragma unroll
        for (int r = 0; r < 8; r++){
            float4 a = *(const float4*)&sA[(mg+r)*FIN + k];
            acc[r].x += a.x*w0.x + a.y*w1.x + a.z*w2.x + a.w*w3.x;
            acc[r].y += a.x*w0.y + a.y*w1.y + a.z*w2.y + a.w*w3.y;
            acc[r].z += a.x*w0.z + a.y*w1.z + a.z*w2.z + a.w*w3.z;
            acc[r].w += a.x*w0.w + a.y*w1.w + a.z*w2.w + a.w*w3.w;
        }
    }
    float s = 0.f, s2 = 0.f;
    #pragma unroll
    for (int r = 0; r < 8; r++){
        *(float4*)&out[(m0+mg+r)*CC + c] = acc[r];
        s  += acc[r].x + acc[r].y + acc[r].z + acc[r].w;
        s2 += acc[r].x*acc[r].x + acc[r].y*acc[r].y
            + acc[r].z*acc[r].z + acc[r].w*acc[r].w;
    }
    __syncthreads();
    float* red = sA;            // reuse
    red[tid] = s; red[256+tid] = s2;
    __syncthreads();
    for (int off = 128; off > 0; off >>= 1){
        if (tid < off){ red[tid] += red[tid+off]; red[256+tid] += red[256+tid+off]; }
        __syncthreads();
    }
    if (tid == 0){
        atomicAdd(&g_acc[isY ? 2 : 0], (double)red[0]);
        atomicAdd(&g_acc[isY ? 3 : 1], (double)red[256]);
    }
}

// ---------------- y_p = relu(q * relu(LN(ys) @ V)) ---------------------------
__global__ __launch_bounds__(256) void k_yp(const float* __restrict__ V,
                                            const float* __restrict__ q){
    int tid = threadIdx.x;
    int row = blockIdx.x*8 + (tid >> 5);   // grid 160 -> 1280 rows
    int k = tid & 31;
    float m, r; get_stats(1, m, r);
    const float* ys = &g_ys[row*CC];
    float acc = 0.f;
    #pragma unroll 4
    for (int d = 0; d < CC; d++) acc += (ys[d]-m)*r * V[d*KK + k];
    float t = fmaxf(acc, 0.f);
    g_yp[row*KK + k] = fmaxf(q[k]*t, 0.f);
}

// ---------------- kA: x_p = relu(x@U), I = x_p @ y_p^T ; FINAL fuses readout --
// 128-row tiles; x staged in two 64-col halves -> 48KB dyn smem -> 4 CTAs/SM.
// !FINAL epilogue also emits per-tile (colmax, expsum) -> no separate kBl pass.
template<bool FINAL, bool NORM>
__global__ __launch_bounds__(256, 4) void kA(const float* __restrict__ U,
                                             int layer, float* __restrict__ outp)
{
    extern __shared__ __align__(16) float S[];
    float* UsS = S;             // CC*KK floats (16KB), [d][k]
    float* xS  = S + CC*KK;     // 128*64 floats (32KB), xor-swizzled half tile
    int tid = threadIdx.x;
    long m0 = (long)blockIdx.x * 128;
    int b = (int)(m0 >> 12);

    float mean = 0.f, rstd = 1.f;
    if (NORM) get_stats(0, mean, rstd);

    for (int i = tid; i < CC*KK; i += 256) UsS[i] = U[i];

    int kg = (tid & 7) * 4;
    int rg = (tid >> 3) * 4;
    int sw = ((rg >> 2) & 3) * 4;       // constant per thread
    float4 acc[4];
    #pragma unroll
    for (int i = 0; i < 4; i++) acc[i] = make_float4(0.f,0.f,0.f,0.f);

    #pragma unroll
    for (int dh = 0; dh < 2; dh++){
        __syncthreads();
        // stage half tile: 128 rows x 64 cols
        #pragma unroll
        for (int t = 0; t < 8; t++){
            int i = tid + t*256;        // 0..2047
            int m = i >> 4; int c4 = (i & 15) * 4;
            float4 v = *(const float4*)&g_x[(m0+m)*CC + dh*64 + c4];
            if (NORM){
                v.x = (v.x-mean)*rstd; v.y = (v.y-mean)*rstd;
                v.z = (v.z-mean)*rstd; v.w = (v.w-mean)*rstd;
            }
            *(float4*)&xS[m*64 + (c4 ^ (((m >> 2) & 3) * 4))] = v;
        }
        __syncthreads();

        #pragma unroll 4
        for (int d = 0; d < 64; d += 4){
            int du = dh*64 + d;
            float4 u0 = *(const float4*)&UsS[(du+0)*KK + kg];
            float4 u1 = *(const float4*)&UsS[(du+1)*KK + kg];
            float4 u2 = *(const float4*)&UsS[(du+2)*KK + kg];
            float4 u3 = *(const float4*)&UsS[(du+3)*KK + kg];
            float4 xr[4];
            #pragma unroll
            for (int i = 0; i < 4; i++)
                xr[i] = *(const float4*)&xS[(rg+i)*64 + (d ^ sw)];
            #pragma unroll
            for (int i = 0; i < 4; i++){
                acc[i].x += xr[i].x*u0.x + xr[i].y*u1.x + xr[i].z*u2.x + xr[i].w*u3.x;
                acc[i].y += xr[i].x*u0.y + xr[i].y*u1.y + xr[i].z*u2.y + xr[i].w*u3.y;
                acc[i].z += xr[i].x*u0.z + xr[i].y*u1.z + xr[i].z*u2.z + xr[i].w*u3.z;
                acc[i].w += xr[i].x*u0.w + xr[i].y*u1.w + xr[i].z*u2.w + xr[i].w*u3.w;
            }
        }
    }
    #pragma unroll
    for (int i = 0; i < 4; i++){
        acc[i].x = fmaxf(acc[i].x, 0.f); acc[i].y = fmaxf(acc[i].y, 0.f);
        acc[i].z = fmaxf(acc[i].z, 0.f); acc[i].w = fmaxf(acc[i].w, 0.f);
    }
    __syncthreads();

    // phase2 smem repartition (45.5KB <= 48KB)
    float* xpS  = S;                           // [128][36]
    float* ypS  = S + 128*36;                  // [40][36]
    float* iS   = S + 128*36 + 40*36;          // [128*40]
    float* sred = iS + 128*40;                 // [160]
    float* mxT  = sred + 160;                  // [40]

    #pragma unroll
    for (int i = 0; i < 4; i++)
        *(float4*)&xpS[(rg+i)*36 + kg] = acc[i];
    for (int i = tid; i < JJ*KK; i += 256){
        int j = i >> 5, k2 = i & 31;
        ypS[j*36 + k2] = g_yp[b*JJ*KK + i];
    }
    __syncthreads();

    // phase2: I[m][j], 4m x 5j per thread, float4 over k
    {
        int mgt = tid >> 3;          // 0..31 -> rows mgt*4..+3
        int jg  = (tid & 7) * 5;     // j base
        float a[4][5];
        #pragma unroll
        for (int i = 0; i < 4; i++)
            #pragma unroll
            for (int jj = 0; jj < 5; jj++) a[i][jj] = 0.f;
        #pragma unroll
        for (int k = 0; k < KK; k += 4){
            float4 xp4[4], yp4[5];
            #pragma unroll
            for (int i = 0; i < 4; i++)
                xp4[i] = *(const float4*)&xpS[(mgt*4+i)*36 + k];
            #pragma unroll
            for (int jj = 0; jj < 5; jj++)
                yp4[jj] = *(const float4*)&ypS[(jg+jj)*36 + k];
            #pragma unroll
            for (int i = 0; i < 4; i++)
                #pragma unroll
                for (int jj = 0; jj < 5; jj++)
                    a[i][jj] += xp4[i].x*yp4[jj].x + xp4[i].y*yp4[jj].y
                              + xp4[i].z*yp4[jj].z + xp4[i].w*yp4[jj].w;
        }
        #pragma unroll
        for (int i = 0; i < 4; i++)
            #pragma unroll
            for (int jj = 0; jj < 5; jj++)
                iS[(mgt*4+i)*40 + jg + jj] = a[i][jj];
    }
    __syncthreads();

    if (!FINAL){
        // coalesced I writeback
        const float4* iv4 = (const float4*)iS;
        float4* Ig4 = (float4*)(g_I + m0*JJ);
        #pragma unroll
        for (int t = 0; t < 5; t++) Ig4[tid + t*256] = iv4[tid + t*256];
        // column max (tile-local)
        if (tid < 160){
            int j = tid % 40, seg = tid / 40;
            float mx = -3.4e38f;
            #pragma unroll 8
            for (int r = 0; r < 32; r++) mx = fmaxf(mx, iS[(seg*32+r)*40 + j]);
            sred[tid] = mx;
        }
        __syncthreads();
        if (tid < 40)
            mxT[tid] = fmaxf(fmaxf(sred[tid], sred[40+tid]),
                             fmaxf(sred[80+tid], sred[120+tid]));
        __syncthreads();
        // column expsum vs tile-local max
        if (tid < 160){
            int j = tid % 40, seg = tid / 40;
            float M = mxT[j];
            float s = 0.f;
            #pragma unroll 8
            for (int r = 0; r < 32; r++) s += __expf(iS[(seg*32+r)*40 + j] - M);
            sred[tid] = s;
        }
        __syncthreads();
        if (tid < 40){
            float s = sred[tid] + sred[40+tid] + sred[80+tid] + sred[120+tid];
            g_tstat[layer][blockIdx.x*JJ + tid] = make_float2(mxT[tid], s);
        }
    } else {
        // p = I @ y_p ; out = sigmoid(dot(x_p, p)); 2 threads per node
        int m  = tid >> 1;
        int kh = (tid & 1) * 16;
        float4 p0 = make_float4(0.f,0.f,0.f,0.f), p1 = p0, p2 = p0, p3 = p0;
        #pragma unroll
        for (int j = 0; j < JJ; j++){
            float iv = iS[m*40 + j];
            float4 y0 = *(const float4*)&ypS[j*36 + kh + 0];
            float4 y1 = *(const float4*)&ypS[j*36 + kh + 4];
            float4 y2 = *(const float4*)&ypS[j*36 + kh + 8];
            float4 y3 = *(const float4*)&ypS[j*36 + kh + 12];
            p0.x += iv*y0.x; p0.y += iv*y0.y; p0.z += iv*y0.z; p0.w += iv*y0.w;
            p1.x += iv*y1.x; p1.y += iv*y1.y; p1.z += iv*y1.z; p1.w += iv*y1.w;
            p2.x += iv*y2.x; p2.y += iv*y2.y; p2.z += iv*y2.z; p2.w += iv*y2.w;
            p3.x += iv*y3.x; p3.y += iv*y3.y; p3.z += iv*y3.z; p3.w += iv*y3.w;
        }
        float4 x0 = *(const float4*)&xpS[m*36 + kh + 0];
        float4 x1 = *(const float4*)&xpS[m*36 + kh + 4];
        float4 x2 = *(const float4*)&xpS[m*36 + kh + 8];
        float4 x3 = *(const float4*)&xpS[m*36 + kh + 12];
        float dot = x0.x*p0.x + x0.y*p0.y + x0.z*p0.z + x0.w*p0.w
                  + x1.x*p1.x + x1.y*p1.y + x1.z*p1.z + x1.w*p1.w
                  + x2.x*p2.x + x2.y*p2.y + x2.z*p2.z + x2.w*p2.w
                  + x3.x*p3.x + x3.y*p3.y + x3.z*p3.z + x3.w*p3.w;
        dot += __shfl_down_sync(0xffffffffu, dot, 1);
        if (!(tid & 1)) outp[m0 + m] = sigm(dot);
    }
}

// ---------------- k_red: merge 32 tile-stats per graph column -----------------
__global__ void k_red(int layer){
    int b = blockIdx.x;          // graph
    int j = threadIdx.x;         // column
    if (j >= JJ) return;
    const float2* ts = &g_tstat[layer][(long)b*32*JJ + j];
    float M = -3.4e38f;
    #pragma unroll
    for (int t = 0; t < 32; t++) M = fmaxf(M, ts[t*JJ].x);
    float S = 0.f;
    #pragma unroll
    for (int t = 0; t < 32; t++){
        float2 v = ts[t*JJ];
        S += v.y * __expf(v.x - M);
    }
    g_maxf[layer][b*JJ + j] = M;
    g_sumb[layer][b*JJ + j] = S;
}

// ---------------- kC: h=relu(A@y_p); h@V^T; gate; x update -------------------
template<bool NORM>
__global__ __launch_bounds__(256) void kC(const float* __restrict__ V,
                                          const float* __restrict__ gW,
                                          const float* __restrict__ gb, int layer)
{
    __shared__ __align__(16) float eS[64*JJ];     // softmax weights
    __shared__ __align__(16) float ypS[JJ*33];
    __shared__ __align__(16) float HS[64*KK];
    __shared__ __align__(16) float VtS[KK*CC];    // [k][d]
    __shared__ float invs[JJ];
    __shared__ float mxs[JJ];
    int tid = threadIdx.x;
    long m0 = (long)blockIdx.x * 64;
    int b = (int)(m0 >> 12);

    float mean = 0.f, rstd = 1.f;
    if (NORM) get_stats(0, mean, rstd);

    if (tid < JJ){
        invs[tid] = 1.f / g_sumb[layer][b*JJ + tid];
        mxs[tid]  = g_maxf[layer][b*JJ + tid];
    }
    for (int i = tid; i < JJ*KK; i += 256){
        int j = i >> 5, k = i & 31;
        ypS[j*33 + k] = g_yp[b*JJ*KK + i];
    }
    for (int i = tid; i < KK*CC; i += 256){
        int d = i >> 5, k = i & 31;
        VtS[k*CC + d] = V[i];
    }
    __syncthreads();
    const float* Ig = &g_I[m0*JJ];
    #pragma unroll
    for (int t = 0; t < 10; t++){
        int idx = tid + t*256;
        int j = idx % 40;
        eS[idx] = __expf(Ig[idx] - mxs[j]) * invs[j];
    }
    __syncthreads();

    // H[m][k] = relu(sum_j a * yp), float4 over j
    int k = tid & 31;
    int mg = (tid >> 5) * 8;
    float h[8];
    #pragma unroll
    for (int r = 0; r < 8; r++) h[r] = 0.f;
    #pragma unroll
    for (int j = 0; j < JJ; j += 4){
        float yv0 = ypS[(j+0)*33 + k];
        float yv1 = ypS[(j+1)*33 + k];
        float yv2 = ypS[(j+2)*33 + k];
        float yv3 = ypS[(j+3)*33 + k];
        #pragma unroll
        for (int r = 0; r < 8; r++){
            float4 e4 = *(const float4*)&eS[(mg+r)*40 + j];
            h[r] += e4.x*yv0 + e4.y*yv1 + e4.z*yv2 + e4.w*yv3;
        }
    }
    #pragma unroll
    for (int r = 0; r < 8; r++) HS[(mg+r)*KK + k] = fmaxf(h[r], 0.f);
    __syncthreads();

    // hC = H @ V^T ; gate ; update
    int d4 = (tid & 31) * 4;
    float4 xv[8], acc[8];
    #pragma unroll
    for (int r = 0; r < 8; r++){
        xv[r] = *(const float4*)&g_x[(m0+mg+r)*CC + d4];
        if (NORM){
            xv[r].x = (xv[r].x-mean)*rstd; xv[r].y = (xv[r].y-mean)*rstd;
            xv[r].z = (xv[r].z-mean)*rstd; xv[r].w = (xv[r].w-mean)*rstd;
        }
        acc[r] = make_float4(0.f,0.f,0.f,0.f);
    }
    #pragma unroll 8
    for (int k2 = 0; k2 < KK; k2++){
        float4 vv = *(const float4*)&VtS[k2*CC + d4];
        #pragma unroll
        for (int r = 0; r < 8; r++){
            float hh = HS[(mg+r)*KK + k2];
            acc[r].x += hh*vv.x; acc[r].y += hh*vv.y;
            acc[r].z += hh*vv.z; acc[r].w += hh*vv.w;
        }
    }
    float4 g1 = *(const float4*)&gW[d4];
    float4 g2 = *(const float4*)&gW[CC + d4];
    float gbv = gb[0];
    #pragma unroll
    for (int r = 0; r < 8; r++){
        float t = xv[r].x*g1.x + xv[r].y*g1.y + xv[r].z*g1.z + xv[r].w*g1.w
                + acc[r].x*g2.x + acc[r].y*g2.y + acc[r].z*g2.z + acc[r].w*g2.w;
        #pragma unroll
        for (int off = 16; off >= 1; off >>= 1)
            t += __shfl_xor_sync(0xffffffffu, t, off);
        float z = sigm(t + gbv);
        float4 nx;
        nx.x = xv[r].x + z*(acc[r].x - xv[r].x);
        nx.y = xv[r].y + z*(acc[r].y - xv[r].y);
        nx.z = xv[r].z + z*(acc[r].z - xv[r].z);
        nx.w = xv[r].w + z*(acc[r].w - xv[r].w);
        *(float4*)&g_x[(m0+mg+r)*CC + d4] = nx;
    }
}

// ---------------- launch ------------------------------------------------------
extern "C" void kernel_launch(void* const* d_in, const int* in_sizes, int n_in,
                              void* d_out, int out_size)
{
    const float* node = (const float*)d_in[0];
    const float* frag = (const float*)d_in[1];
    const float* Wi   = (const float*)d_in[2];
    const float* bi   = (const float*)d_in[3];
    const float* U    = (const float*)d_in[4];
    const float* V    = (const float*)d_in[5];
    const float* q    = (const float*)d_in[6];
    const float* gW   = (const float*)d_in[7];
    const float* gb   = (const float*)d_in[8];
    float* out = (float*)d_out;

    const int SMEM_A = (CC*KK + 128*64) * 4;   // 49152 bytes
    cudaFuncSetAttribute((const void*)kA<false,true >,
                         cudaFuncAttributeMaxDynamicSharedMemorySize, SMEM_A);
    cudaFuncSetAttribute((const void*)kA<false,false>,
                         cudaFuncAttributeMaxDynamicSharedMemorySize, SMEM_A);
    cudaFuncSetAttribute((const void*)kA<true ,false>,
                         cudaFuncAttributeMaxDynamicSharedMemorySize, SMEM_A);

    k_init<<<1, 32>>>();
    k_in_gemm<<<NXBLK + NYBLK, 256>>>(node, frag, Wi, bi);
    k_yp<<<160, 256>>>(V, q);

    // layer 0 (normalize on the fly)
    kA<false,true ><<<NXB2, 256, SMEM_A>>>(U, 0, nullptr);
    k_red<<<NB, 64>>>(0);
    kC<true ><<<NXBLK, 256>>>(V, gW, gb, 0);
    // layer 1
    kA<false,false><<<NXB2, 256, SMEM_A>>>(U, 1, nullptr);
    k_red<<<NB, 64>>>(1);
    kC<false><<<NXBLK, 256>>>(V, gW, gb, 1);
    // layer 2 (final, fused readout)
    kA<true ,false><<<NXB2, 256, SMEM_A>>>(U, 0, out);
}

// round 16
// speedup vs baseline: 1.1390x; 1.0115x over previous
#include <cuda_runtime.h>

#define NB 32
#define NPG 4096
#define NN (NB*NPG)          /* 131072 */
#define FIN 64
#define CC 128
#define KK 32
#define JJ 40
#define NXBLK (NN/64)        /* 2048 */
#define NYBLK ((NB*JJ)/64)   /* 20 */
#define NXB2 (NN/128)        /* 1024 */

// ---------------- scratch (static device globals; no allocation) -------------
__device__ float    g_x[NN*CC];        // xs (raw, then normalized-domain)
__device__ float    g_I[NN*JJ];        // raw I
__device__ float    g_ys[NB*JJ*CC];    // ys raw
__device__ float    g_yp[NB*JJ*KK];    // y_p
__device__ double   g_acc[4];          // sx, sx2, sy, sy2
__device__ float2   g_tstat[2][NXB2*JJ]; // per-tile (colmax, expsum)
__device__ float    g_maxf[2][NB*JJ];  // merged per-graph colmax
__device__ float    g_sumb[2][NB*JJ];  // merged per-graph expsum

__device__ __forceinline__ float sigm(float t){ return 1.f/(1.f+__expf(-t)); }

__device__ __forceinline__ void get_stats(int which, float& m, float& r){
    double s  = g_acc[which*2+0];
    double s2 = g_acc[which*2+1];
    double cnt = which ? (double)(NB*JJ)*(double)CC : (double)NN*(double)CC;
    double mu = s/cnt;
    double var = s2/cnt - mu*mu;
    m = (float)mu;
    r = (float)rsqrt(var + 1e-5);
}

// ---------------- init: zero LN accumulators ---------------------------------
__global__ void k_init(){
    if (threadIdx.x < 4) g_acc[threadIdx.x] = 0.0;
}

// ---------------- input GEMM: out = A[M,64] @ W^T[64,128] + b ----------------
__global__ __launch_bounds__(256) void k_in_gemm(
    const float* __restrict__ node, const float* __restrict__ frag,
    const float* __restrict__ W, const float* __restrict__ bias)
{
    int bx = blockIdx.x;
    bool isY = (bx >= NXBLK);
    const float* __restrict__ A   = isY ? frag : node;
    float* __restrict__       out = isY ? g_ys : g_x;
    long m0 = (long)(isY ? bx - NXBLK : bx) * 64;

    __shared__ __align__(16) float sW[FIN*CC];  // [k][n]
    __shared__ __align__(16) float sA[64*FIN];  // [m][k]
    int tid = threadIdx.x;

    for (int i = tid; i < FIN*CC; i += 256){
        int n = i >> 6, k = i & 63;
        sW[k*CC + n] = W[i];
    }
    for (int i = tid; i < 64*FIN; i += 256) sA[i] = A[m0*FIN + i];
    __syncthreads();

    int c  = (tid & 31) * 4;
    int mg = (tid >> 5) * 8;
    float4 bb = *(const float4*)&bias[c];
    float4 acc[8];
    #pragma unroll
    for (int r = 0; r < 8; r++) acc[r] = bb;

    #pragma unroll 4
    for (int k = 0; k < FIN; k += 4){
        float4 w0 = *(const float4*)&sW[(k+0)*CC + c];
        float4 w1 = *(const float4*)&sW[(k+1)*CC + c];
        float4 w2 = *(const float4*)&sW[(k+2)*CC + c];
        float4 w3 = *(const float4*)&sW[(k+3)*CC + c];
        #pragma unroll
        for (int r = 0; r < 8; r++){
            float4 a = *(const float4*)&sA[(mg+r)*FIN + k];
            acc[r].x += a.x*w0.x + a.y*w1.x + a.z*w2.x + a.w*w3.x;
            acc[r].y += a.x*w0.y + a.y*w1.y + a.z*w2.y + a.w*w3.y;
            acc[r].z += a.x*w0.z + a.y*w1.z + a.z*w2.z + a.w*w3.z;
            acc[r].w += a.x*w0.w + a.y*w1.w + a.z*w2.w + a.w*w3.w;
        }
    }
    float s = 0.f, s2 = 0.f;
    #pragma unroll
    for (int r = 0; r < 8; r++){
        *(float4*)&out[(m0+mg+r)*CC + c] = acc[r];
        s  += acc[r].x + acc[r].y + acc[r].z + acc[r].w;
        s2 += acc[r].x*acc[r].x + acc[r].y*acc[r].y
            + acc[r].z*acc[r].z + acc[r].w*acc[r].w;
    }
    __syncthreads();
    float* red = sA;            // reuse
    red[tid] = s; red[256+tid] = s2;
    __syncthreads();
    for (int off = 128; off > 0; off >>= 1){
        if (tid < off){ red[tid] += red[tid+off]; red[256+tid] += red[256+tid+off]; }
        __syncthreads();
    }
    if (tid == 0){
        atomicAdd(&g_acc[isY ? 2 : 0], (double)red[0]);
        atomicAdd(&g_acc[isY ? 3 : 1], (double)red[256]);
    }
}

// ---------------- y_p = relu(q * relu(LN(ys) @ V)) ---------------------------
__global__ __launch_bounds__(256) void k_yp(const float* __restrict__ V,
                                            const float* __restrict__ q){
    int tid = threadIdx.x;
    int row = blockIdx.x*8 + (tid >> 5);   // grid 160 -> 1280 rows
    int k = tid & 31;
    float m, r; get_stats(1, m, r);
    const float* ys = &g_ys[row*CC];
    float acc = 0.f;
    #pragma unroll 4
    for (int d = 0; d < CC; d++) acc += (ys[d]-m)*r * V[d*KK + k];
    float t = fmaxf(acc, 0.f);
    g_yp[row*KK + k] = fmaxf(q[k]*t, 0.f);
}

// ---------------- kA: x_p = relu(x@U), I = x_p @ y_p^T ; FINAL fuses readout --
// 128-row tiles; x staged in two 64-col halves -> 48KB dyn smem -> 4 CTAs/SM.
// !FINAL epilogue also emits per-tile (colmax, expsum) -> no separate kBl pass.
template<bool FINAL, bool NORM>
__global__ __launch_bounds__(256, 4) void kA(const float* __restrict__ U,
                                             int layer, float* __restrict__ outp)
{
    extern __shared__ __align__(16) float S[];
    float* UsS = S;             // CC*KK floats (16KB), [d][k]
    float* xS  = S + CC*KK;     // 128*64 floats (32KB), xor-swizzled half tile
    int tid = threadIdx.x;
    long m0 = (long)blockIdx.x * 128;
    int b = (int)(m0 >> 12);

    float mean = 0.f, rstd = 1.f;
    if (NORM) get_stats(0, mean, rstd);

    for (int i = tid; i < CC*KK; i += 256) UsS[i] = U[i];

    int kg = (tid & 7) * 4;
    int rg = (tid >> 3) * 4;
    int sw = ((rg >> 2) & 3) * 4;       // constant per thread
    float4 acc[4];
    #pragma unroll
    for (int i = 0; i < 4; i++) acc[i] = make_float4(0.f,0.f,0.f,0.f);

    #pragma unroll
    for (int dh = 0; dh < 2; dh++){
        __syncthreads();
        // stage half tile: 128 rows x 64 cols
        #pragma unroll
        for (int t = 0; t < 8; t++){
            int i = tid + t*256;        // 0..2047
            int m = i >> 4; int c4 = (i & 15) * 4;
            float4 v = *(const float4*)&g_x[(m0+m)*CC + dh*64 + c4];
            if (NORM){
                v.x = (v.x-mean)*rstd; v.y = (v.y-mean)*rstd;
                v.z = (v.z-mean)*rstd; v.w = (v.w-mean)*rstd;
            }
            *(float4*)&xS[m*64 + (c4 ^ (((m >> 2) & 3) * 4))] = v;
        }
        __syncthreads();

        #pragma unroll 4
        for (int d = 0; d < 64; d += 4){
            int du = dh*64 + d;
            float4 u0 = *(const float4*)&UsS[(du+0)*KK + kg];
            float4 u1 = *(const float4*)&UsS[(du+1)*KK + kg];
            float4 u2 = *(const float4*)&UsS[(du+2)*KK + kg];
            float4 u3 = *(const float4*)&UsS[(du+3)*KK + kg];
            float4 xr[4];
            #pragma unroll
            for (int i = 0; i < 4; i++)
                xr[i] = *(const float4*)&xS[(rg+i)*64 + (d ^ sw)];
            #pragma unroll
            for (int i = 0; i < 4; i++){
                acc[i].x += xr[i].x*u0.x + xr[i].y*u1.x + xr[i].z*u2.x + xr[i].w*u3.x;
                acc[i].y += xr[i].x*u0.y + xr[i].y*u1.y + xr[i].z*u2.y + xr[i].w*u3.y;
                acc[i].z += xr[i].x*u0.z + xr[i].y*u1.z + xr[i].z*u2.z + xr[i].w*u3.z;
                acc[i].w += xr[i].x*u0.w + xr[i].y*u1.w + xr[i].z*u2.w + xr[i].w*u3.w;
            }
        }
    }
    #pragma unroll
    for (int i = 0; i < 4; i++){
        acc[i].x = fmaxf(acc[i].x, 0.f); acc[i].y = fmaxf(acc[i].y, 0.f);
        acc[i].z = fmaxf(acc[i].z, 0.f); acc[i].w = fmaxf(acc[i].w, 0.f);
    }
    __syncthreads();

    // phase2 smem repartition (45.5KB <= 48KB)
    float* xpS  = S;                           // [128][36]
    float* ypS  = S + 128*36;                  // [40][36]
    float* iS   = S + 128*36 + 40*36;          // [128*40]
    float* sred = iS + 128*40;                 // [160]
    float* mxT  = sred + 160;                  // [40]

    #pragma unroll
    for (int i = 0; i < 4; i++)
        *(float4*)&xpS[(rg+i)*36 + kg] = acc[i];
    for (int i = tid; i < JJ*KK; i += 256){
        int j = i >> 5, k2 = i & 31;
        ypS[j*36 + k2] = g_yp[b*JJ*KK + i];
    }
    __syncthreads();

    // phase2: I[m][j], 4m x 5j per thread, float4 over k
    {
        int mgt = tid >> 3;          // 0..31 -> rows mgt*4..+3
        int jg  = (tid & 7) * 5;     // j base
        float a[4][5];
        #pragma unroll
        for (int i = 0; i < 4; i++)
            #pragma unroll
            for (int jj = 0; jj < 5; jj++) a[i][jj] = 0.f;
        #pragma unroll
        for (int k = 0; k < KK; k += 4){
            float4 xp4[4], yp4[5];
            #pragma unroll
            for (int i = 0; i < 4; i++)
                xp4[i] = *(const float4*)&xpS[(mgt*4+i)*36 + k];
            #pragma unroll
            for (int jj = 0; jj < 5; jj++)
                yp4[jj] = *(const float4*)&ypS[(jg+jj)*36 + k];
            #pragma unroll
            for (int i = 0; i < 4; i++)
                #pragma unroll
                for (int jj = 0; jj < 5; jj++)
                    a[i][jj] += xp4[i].x*yp4[jj].x + xp4[i].y*yp4[jj].y
                              + xp4[i].z*yp4[jj].z + xp4[i].w*yp4[jj].w;
        }
        #pragma unroll
        for (int i = 0; i < 4; i++)
            #pragma unroll
            for (int jj = 0; jj < 5; jj++)
                iS[(mgt*4+i)*40 + jg + jj] = a[i][jj];
    }
    __syncthreads();

    if (!FINAL){
        // coalesced I writeback
        const float4* iv4 = (const float4*)iS;
        float4* Ig4 = (float4*)(g_I + m0*JJ);
        #pragma unroll
        for (int t = 0; t < 5; t++) Ig4[tid + t*256] = iv4[tid + t*256];
        // column max (tile-local)
        if (tid < 160){
            int j = tid % 40, seg = tid / 40;
            float mx = -3.4e38f;
            #pragma unroll 8
            for (int r = 0; r < 32; r++) mx = fmaxf(mx, iS[(seg*32+r)*40 + j]);
            sred[tid] = mx;
        }
        __syncthreads();
        if (tid < 40)
            mxT[tid] = fmaxf(fmaxf(sred[tid], sred[40+tid]),
                             fmaxf(sred[80+tid], sred[120+tid]));
        __syncthreads();
        // column expsum vs tile-local max
        if (tid < 160){
            int j = tid % 40, seg = tid / 40;
            float M = mxT[j];
            float s = 0.f;
            #pragma unroll 8
            for (int r = 0; r < 32; r++) s += __expf(iS[(seg*32+r)*40 + j] - M);
            sred[tid] = s;
        }
        __syncthreads();
        if (tid < 40){
            float s = sred[tid] + sred[40+tid] + sred[80+tid] + sred[120+tid];
            g_tstat[layer][blockIdx.x*JJ + tid] = make_float2(mxT[tid], s);
        }
    } else {
        // p = I @ y_p ; out = sigmoid(dot(x_p, p)); 2 threads per node
        int m  = tid >> 1;
        int kh = (tid & 1) * 16;
        float4 p0 = make_float4(0.f,0.f,0.f,0.f), p1 = p0, p2 = p0, p3 = p0;
        #pragma unroll
        for (int j = 0; j < JJ; j++){
            float iv = iS[m*40 + j];
            float4 y0 = *(const float4*)&ypS[j*36 + kh + 0];
            float4 y1 = *(const float4*)&ypS[j*36 + kh + 4];
            float4 y2 = *(const float4*)&ypS[j*36 + kh + 8];
            float4 y3 = *(const float4*)&ypS[j*36 + kh + 12];
            p0.x += iv*y0.x; p0.y += iv*y0.y; p0.z += iv*y0.z; p0.w += iv*y0.w;
            p1.x += iv*y1.x; p1.y += iv*y1.y; p1.z += iv*y1.z; p1.w += iv*y1.w;
            p2.x += iv*y2.x; p2.y += iv*y2.y; p2.z += iv*y2.z; p2.w += iv*y2.w;
            p3.x += iv*y3.x; p3.y += iv*y3.y; p3.z += iv*y3.z; p3.w += iv*y3.w;
        }
        float4 x0 = *(const float4*)&xpS[m*36 + kh + 0];
        float4 x1 = *(const float4*)&xpS[m*36 + kh + 4];
        float4 x2 = *(const float4*)&xpS[m*36 + kh + 8];
        float4 x3 = *(const float4*)&xpS[m*36 + kh + 12];
        float dot = x0.x*p0.x + x0.y*p0.y + x0.z*p0.z + x0.w*p0.w
                  + x1.x*p1.x + x1.y*p1.y + x1.z*p1.z + x1.w*p1.w
                  + x2.x*p2.x + x2.y*p2.y + x2.z*p2.z + x2.w*p2.w
                  + x3.x*p3.x + x3.y*p3.y + x3.z*p3.z + x3.w*p3.w;
        dot += __shfl_down_sync(0xffffffffu, dot, 1);
        if (!(tid & 1)) outp[m0 + m] = sigm(dot);
    }
}

// ---------------- k_red: merge 32 tile-stats per graph column -----------------
__global__ void k_red(int layer){
    int b = blockIdx.x;          // graph
    int j = threadIdx.x;         // column
    if (j >= JJ) return;
    const float2* ts = &g_tstat[layer][(long)b*32*JJ + j];
    float M = -3.4e38f;
    #pragma unroll
    for (int t = 0; t < 32; t++) M = fmaxf(M, ts[t*JJ].x);
    float S = 0.f;
    #pragma unroll
    for (int t = 0; t < 32; t++){
        float2 v = ts[t*JJ];
        S += v.y * __expf(v.x - M);
    }
    g_maxf[layer][b*JJ + j] = M;
    g_sumb[layer][b*JJ + j] = S;
}

// ---------------- kC: h=relu(A@y_p); h@V^T; gate; x update -------------------
template<bool NORM>
__global__ __launch_bounds__(256) void kC(const float* __restrict__ V,
                                          const float* __restrict__ gW,
                                          const float* __restrict__ gb, int layer)
{
    __shared__ __align__(16) float eS[64*JJ];     // softmax weights
    __shared__ __align__(16) float ypS[JJ*33];
    __shared__ __align__(16) float HS[64*KK];
    __shared__ __align__(16) float VtS[KK*CC];    // [k][d]
    __shared__ float invs[JJ];
    __shared__ float mxs[JJ];
    int tid = threadIdx.x;
    long m0 = (long)blockIdx.x * 64;
    int b = (int)(m0 >> 12);

    float mean = 0.f, rstd = 1.f;
    if (NORM) get_stats(0, mean, rstd);

    if (tid < JJ){
        invs[tid] = 1.f / g_sumb[layer][b*JJ + tid];
        mxs[tid]  = g_maxf[layer][b*JJ + tid];
    }
    for (int i = tid; i < JJ*KK; i += 256){
        int j = i >> 5, k = i & 31;
        ypS[j*33 + k] = g_yp[b*JJ*KK + i];
    }
    for (int i = tid; i < KK*CC; i += 256){
        int d = i >> 5, k = i & 31;
        VtS[k*CC + d] = V[i];
    }
    __syncthreads();
    const float* Ig = &g_I[m0*JJ];
    #pragma unroll
    for (int t = 0; t < 10; t++){
        int idx = tid + t*256;
        int j = idx % 40;
        eS[idx] = __expf(Ig[idx] - mxs[j]) * invs[j];
    }
    __syncthreads();

    // H[m][k] = relu(sum_j a * yp), float4 over j
    int k = tid & 31;
    int mg = (tid >> 5) * 8;
    float h[8];
    #pragma unroll
    for (int r = 0; r < 8; r++) h[r] = 0.f;
    #pragma unroll
    for (int j = 0; j < JJ; j += 4){
        float yv0 = ypS[(j+0)*33 + k];
        float yv1 = ypS[(j+1)*33 + k];
        float yv2 = ypS[(j+2)*33 + k];
        float yv3 = ypS[(j+3)*33 + k];
        #pragma unroll
        for (int r = 0; r < 8; r++){
            float4 e4 = *(const float4*)&eS[(mg+r)*40 + j];
            h[r] += e4.x*yv0 + e4.y*yv1 + e4.z*yv2 + e4.w*yv3;
        }
    }
    #pragma unroll
    for (int r = 0; r < 8; r++) HS[(mg+r)*KK + k] = fmaxf(h[r], 0.f);
    __syncthreads();

    // hC = H @ V^T ; gate ; update
    int d4 = (tid & 31) * 4;
    float4 xv[8], acc[8];
    #pragma unroll
    for (int r = 0; r < 8; r++){
        xv[r] = *(const float4*)&g_x[(m0+mg+r)*CC + d4];
        if (NORM){
            xv[r].x = (xv[r].x-mean)*rstd; xv[r].y = (xv[r].y-mean)*rstd;
            xv[r].z = (xv[r].z-mean)*rstd; xv[r].w = (xv[r].w-mean)*rstd;
        }
        acc[r] = make_float4(0.f,0.f,0.f,0.f);
    }
    #pragma unroll 8
    for (int k2 = 0; k2 < KK; k2++){
        float4 vv = *(const float4*)&VtS[k2*CC + d4];
        #pragma unroll
        for (int r = 0; r < 8; r++){
            float hh = HS[(mg+r)*KK + k2];
            acc[r].x += hh*vv.x; acc[r].y += hh*vv.y;
            acc[r].z += hh*vv.z; acc[r].w += hh*vv.w;
        }
    }
    float4 g1 = *(const float4*)&gW[d4];
    float4 g2 = *(const float4*)&gW[CC + d4];
    float gbv = gb[0];
    #pragma unroll
    for (int r = 0; r < 8; r++){
        float t = xv[r].x*g1.x + xv[r].y*g1.y + xv[r].z*g1.z + xv[r].w*g1.w
                + acc[r].x*g2.x + acc[r].y*g2.y + acc[r].z*g2.z + acc[r].w*g2.w;
        #pragma unroll
        for (int off = 16; off >= 1; off >>= 1)
            t += __shfl_xor_sync(0xffffffffu, t, off);
        float z = sigm(t + gbv);
        float4 nx;
        nx.x = xv[r].x + z*(acc[r].x - xv[r].x);
        nx.y = xv[r].y + z*(acc[r].y - xv[r].y);
        nx.z = xv[r].z + z*(acc[r].z - xv[r].z);
        nx.w = xv[r].w + z*(acc[r].w - xv[r].w);
        *(float4*)&g_x[(m0+mg+r)*CC + d4] = nx;
    }
}

// ---------------- launch ------------------------------------------------------
extern "C" void kernel_launch(void* const* d_in, const int* in_sizes, int n_in,
                              void* d_out, int out_size)
{
    const float* node = (const float*)d_in[0];
    const float* frag = (const float*)d_in[1];
    const float* Wi   = (const float*)d_in[2];
    const float* bi   = (const float*)d_in[3];
    const float* U    = (const float*)d_in[4];
    const float* V    = (const float*)d_in[5];
    const float* q    = (const float*)d_in[6];
    const float* gW   = (const float*)d_in[7];
    const float* gb   = (const float*)d_in[8];
    float* out = (float*)d_out;

    const int SMEM_A = (CC*KK + 128*64) * 4;   // 49152 bytes
    cudaFuncSetAttribute((const void*)kA<false,true >,
                         cudaFuncAttributeMaxDynamicSharedMemorySize, SMEM_A);
    cudaFuncSetAttribute((const void*)kA<false,false>,
                         cudaFuncAttributeMaxDynamicSharedMemorySize, SMEM_A);
    cudaFuncSetAttribute((const void*)kA<true ,false>,
                         cudaFuncAttributeMaxDynamicSharedMemorySize, SMEM_A);

    k_init<<<1, 32>>>();
    k_in_gemm<<<NXBLK + NYBLK, 256>>>(node, frag, Wi, bi);
    k_yp<<<160, 256>>>(V, q);

    // layer 0 (normalize on the fly)
    kA<false,true ><<<NXB2, 256, SMEM_A>>>(U, 0, nullptr);
    k_red<<<NB, 64>>>(0);
    kC<true ><<<NXBLK, 256>>>(V, gW, gb, 0);
    // layer 1
    kA<false,false><<<NXB2, 256, SMEM_A>>>(U, 1, nullptr);
    k_red<<<NB, 64>>>(1);
    kC<false><<<NXBLK, 256>>>(V, gW, gb, 1);
    // layer 2 (final, fused readout)
    kA<true ,false><<<NXB2, 256, SMEM_A>>>(U, 0, out);
}